// round 6
// baseline (speedup 1.0000x reference)
#include <cuda_runtime.h>

#define MAXN     131072          // >= N (100000), sized with margin
#define HID      128
#define ODIM     400
#define NBLOCKS  592             // 4 per SM * 148 — all co-resident (cap is 8/SM)
#define NTHREADS 256

// Scratch (no cudaMalloc) — device globals, zero-filled at module load.
__device__ unsigned g_degi[MAXN];
__device__ float    g_dinv[MAXN];
__device__ float    g_y[MAXN];      // y[r] = dinv[r] * x[r]
__device__ float    g_sacc[MAXN];
__device__ float    g_tacc[MAXN];
__device__ float    g_v[HID];
__device__ unsigned g_bar_count;    // software grid barrier state
__device__ volatile int g_bar_sense;

// Sense-reversing grid barrier. All NBLOCKS are resident (launch_bounds).
// Called an EVEN number of times per launch so persistent state returns to
// {0,0} for the next graph replay.
__device__ __forceinline__ void grid_barrier(int& local_sense) {
    __syncthreads();
    if (threadIdx.x == 0) {
        int s = local_sense ^ 1;
        __threadfence();                               // release prior writes
        unsigned arrived = atomicAdd(&g_bar_count, 1u);
        if (arrived == NBLOCKS - 1) {
            g_bar_count = 0;
            __threadfence();
            g_bar_sense = s;
        } else {
            while (g_bar_sense != s) { }
        }
        __threadfence();                               // acquire
    }
    __syncthreads();
    local_sense ^= 1;
}

__global__ void __launch_bounds__(NTHREADS, 8)
k_fused(const float* __restrict__ x,
        const int* __restrict__ row, const int* __restrict__ col,
        const float* __restrict__ W1, const float* __restrict__ b1,
        const float* __restrict__ W2, const float* __restrict__ b2,
        float* __restrict__ out, int n, int E, int vec_ok) {
    const int tid    = threadIdx.x;
    const int gtid   = blockIdx.x * NTHREADS + tid;
    const int stride = NBLOCKS * NTHREADS;
    int sense = 0;

    // ---- P1: degree count over destinations (RED only, no return) --------
    for (int e = gtid * 4; e < E; e += stride * 4) {
        if (vec_ok && e + 3 < E) {
            int4 c = *reinterpret_cast<const int4*>(col + e);
            atomicAdd(&g_degi[c.x], 1u);
            atomicAdd(&g_degi[c.y], 1u);
            atomicAdd(&g_degi[c.z], 1u);
            atomicAdd(&g_degi[c.w], 1u);
        } else {
            int lim = min(e + 4, E);
            for (int k = e; k < lim; k++) atomicAdd(&g_degi[col[k]], 1u);
        }
    }
    grid_barrier(sense);   // B1

    // ---- P2: dinv, y, and (re)initialize all accumulators ----------------
    for (int i = gtid; i < n; i += stride) {
        unsigned d = g_degi[i];
        float di = rsqrtf((float)(d + 1u));        // +1 = self loop
        g_dinv[i] = di;
        g_y[i]    = di * x[i];
        g_sacc[i] = 0.0f;
        g_tacc[i] = 0.0f;
        g_degi[i] = 0u;                            // restore entry invariant
    }
    if (gtid < HID) g_v[gtid] = 0.0f;
    grid_barrier(sense);   // B2

    // ---- P3: fused edge pass: independent gathers + fire-and-forget REDs -
    //   sacc[c] += y[r];  tacc[r] += dinv[c]
    for (int e = gtid * 4; e < E; e += stride * 4) {
        if (vec_ok && e + 3 < E) {
            int4 r = *reinterpret_cast<const int4*>(row + e);
            int4 c = *reinterpret_cast<const int4*>(col + e);
            // all 8 gathers independent -> full MLP, L2-resident hits
            float y0 = __ldg(&g_y[r.x]);
            float y1 = __ldg(&g_y[r.y]);
            float y2 = __ldg(&g_y[r.z]);
            float y3 = __ldg(&g_y[r.w]);
            float d0 = __ldg(&g_dinv[c.x]);
            float d1 = __ldg(&g_dinv[c.y]);
            float d2 = __ldg(&g_dinv[c.z]);
            float d3 = __ldg(&g_dinv[c.w]);
            atomicAdd(&g_sacc[c.x], y0);
            atomicAdd(&g_sacc[c.y], y1);
            atomicAdd(&g_sacc[c.z], y2);
            atomicAdd(&g_sacc[c.w], y3);
            atomicAdd(&g_tacc[r.x], d0);
            atomicAdd(&g_tacc[r.y], d1);
            atomicAdd(&g_tacc[r.z], d2);
            atomicAdd(&g_tacc[r.w], d3);
        } else {
            int lim = min(e + 4, E);
            for (int k = e; k < lim; k++) {
                int r = row[k], c = col[k];
                atomicAdd(&g_sacc[c], __ldg(&g_y[r]));
                atomicAdd(&g_tacc[r], __ldg(&g_dinv[c]));
            }
        }
    }
    grid_barrier(sense);   // B3

    // ---- P4: v[f] = sum_i t[i] * relu(s[i]*W1[f] + b1[f]) ----------------
    //   s[i] = di*(sacc[i] + y[i]);  t[i] = di*(tacc[i] + di)
    {
        __shared__ float ssh[NTHREADS];
        __shared__ float tsh[NTHREADS];
        const int f    = tid & (HID - 1);
        const int half = tid >> 7;               // 0 or 1
        float w  = W1[f];
        float bb = b1[f];
        float acc = 0.0f;

        for (int base = blockIdx.x * NTHREADS; base < n; base += NBLOCKS * NTHREADS) {
            int i = base + tid;
            float sv = 0.0f, tv = 0.0f;
            if (i < n) {
                float di = g_dinv[i];
                sv = di * (g_sacc[i] + g_y[i]);
                tv = di * (g_tacc[i] + di);
            }
            __syncthreads();
            ssh[tid] = sv;
            tsh[tid] = tv;
            __syncthreads();
            int lim = min(NTHREADS, n - base);
            int j0   = half * HID;
            int jend = min(lim, j0 + HID);
            #pragma unroll 8
            for (int j = j0; j < jend; j++) {
                float h = fmaxf(fmaf(ssh[j], w, bb), 0.0f);
                acc = fmaf(tsh[j], h, acc);
            }
            __syncthreads();
        }
        atomicAdd(&g_v[f], acc);
    }
    grid_barrier(sense);   // B4 (4 barriers total — even)

    // ---- P5: out[o] = (1/n) * sum_f v[f]*W2[f,o] + b2[o] -----------------
    if (blockIdx.x < 2) {
        __shared__ float vsh[HID];
        if (tid < HID) vsh[tid] = g_v[tid];
        __syncthreads();
        int o = blockIdx.x * NTHREADS + tid;
        if (o < ODIM) {
            float acc = 0.0f;
            #pragma unroll 16
            for (int f = 0; f < HID; f++)
                acc = fmaf(vsh[f], W2[f * ODIM + o], acc);
            out[o] = acc * (1.0f / (float)n) + b2[o];
        }
    }
}

// ---------------------------------------------------------------------------
extern "C" void kernel_launch(void* const* d_in, const int* in_sizes, int n_in,
                              void* d_out, int out_size) {
    const float* x  = (const float*)d_in[0];   // [N,1]
    const int*   ei = (const int*)d_in[1];     // [2,E]: row half then col half
    const float* W1 = (const float*)d_in[2];   // [1,128]
    const float* b1 = (const float*)d_in[3];   // [128]
    const float* W2 = (const float*)d_in[4];   // [128,400]
    const float* b2 = (const float*)d_in[5];   // [400]
    float* out = (float*)d_out;                // [400]

    int n = in_sizes[0];
    int E = in_sizes[1] / 2;
    const int* row = ei;
    const int* col = ei + E;
    int vec_ok = ((E & 3) == 0) ? 1 : 0;       // col half stays 16B-aligned

    k_fused<<<NBLOCKS, NTHREADS>>>(x, row, col, W1, b1, W2, b2, out, n, E, vec_ok);
}

// round 7
// speedup vs baseline: 1.3146x; 1.3146x over previous
#include <cuda_runtime.h>

#define MAXN 131072
#define HID  128
#define ODIM 400

// Scratch (no cudaMalloc allowed) — device globals.
__device__ unsigned g_degi[MAXN];
__device__ float    g_dinv[MAXN];
__device__ float    g_y[MAXN];      // y[r] = dinv[r] * x[r]
__device__ float    g_sacc[MAXN];
__device__ float    g_tacc[MAXN];
__device__ float    g_v[HID];

// ---------------------------------------------------------------------------
// 1) init: deg counter 0, accumulators 0
__global__ void k_init(int n) {
    int i = blockIdx.x * blockDim.x + threadIdx.x;
    if (i < n) {
        g_degi[i] = 0u;
        g_sacc[i] = 0.0f;
        g_tacc[i] = 0.0f;
    }
    if (i < HID) g_v[i] = 0.0f;
}

// ---------------------------------------------------------------------------
// 2) degree count over destinations (col). 4 edges/thread -> ~8 blocks/SM.
__global__ void __launch_bounds__(256, 8)
k_deg(const int* __restrict__ col, int E, int vec_ok) {
    int i = blockIdx.x * blockDim.x + threadIdx.x;
    int e = i * 4;
    if (vec_ok && e + 3 < E) {
        int4 c = *reinterpret_cast<const int4*>(col + e);
        atomicAdd(&g_degi[c.x], 1u);
        atomicAdd(&g_degi[c.y], 1u);
        atomicAdd(&g_degi[c.z], 1u);
        atomicAdd(&g_degi[c.w], 1u);
    } else if (e < E) {
        int lim = min(e + 4, E);
        for (int k = e; k < lim; k++) atomicAdd(&g_degi[col[k]], 1u);
    }
}

// ---------------------------------------------------------------------------
// 3) dinv = rsqrt(deg + 1 self loop); y = dinv * x
__global__ void k_dinv(const float* __restrict__ x, int n) {
    int i = blockIdx.x * blockDim.x + threadIdx.x;
    if (i < n) {
        float di = rsqrtf((float)(g_degi[i] + 1u));
        g_dinv[i] = di;
        g_y[i]    = di * x[i];
    }
}

// ---------------------------------------------------------------------------
// 4) fused edge pass: independent gathers + fire-and-forget REDs.
//    sacc[c] += y[r];  tacc[r] += dinv[c]
//    4 edges/thread -> 1563 blocks -> ~full occupancy.
__global__ void __launch_bounds__(256, 8)
k_edge(const int* __restrict__ row, const int* __restrict__ col,
       int E, int vec_ok) {
    int i = blockIdx.x * blockDim.x + threadIdx.x;
    int e = i * 4;
    if (vec_ok && e + 3 < E) {
        int4 r = *reinterpret_cast<const int4*>(row + e);
        int4 c = *reinterpret_cast<const int4*>(col + e);
        // 8 independent gathers (full MLP), then 8 non-returning REDs
        float y0 = __ldg(&g_y[r.x]);
        float y1 = __ldg(&g_y[r.y]);
        float y2 = __ldg(&g_y[r.z]);
        float y3 = __ldg(&g_y[r.w]);
        float d0 = __ldg(&g_dinv[c.x]);
        float d1 = __ldg(&g_dinv[c.y]);
        float d2 = __ldg(&g_dinv[c.z]);
        float d3 = __ldg(&g_dinv[c.w]);
        atomicAdd(&g_sacc[c.x], y0);
        atomicAdd(&g_sacc[c.y], y1);
        atomicAdd(&g_sacc[c.z], y2);
        atomicAdd(&g_sacc[c.w], y3);
        atomicAdd(&g_tacc[r.x], d0);
        atomicAdd(&g_tacc[r.y], d1);
        atomicAdd(&g_tacc[r.z], d2);
        atomicAdd(&g_tacc[r.w], d3);
    } else if (e < E) {
        int lim = min(e + 4, E);
        for (int k = e; k < lim; k++) {
            int r = row[k], c = col[k];
            atomicAdd(&g_sacc[c], __ldg(&g_y[r]));
            atomicAdd(&g_tacc[r], __ldg(&g_dinv[c]));
        }
    }
}

// ---------------------------------------------------------------------------
// 5) v[f] = sum_i t[i] * relu(s[i]*W1[f] + b1[f])
//    s[i] = di*(sacc[i] + y[i]);  t[i] = di*(tacc[i] + di)
__global__ void k_v(const float* __restrict__ W1, const float* __restrict__ b1,
                    int n) {
    __shared__ float ssh[128];
    __shared__ float tsh[128];
    int f = threadIdx.x;
    float w  = W1[f];
    float bb = b1[f];
    float acc = 0.0f;

    for (int base = blockIdx.x * 128; base < n; base += gridDim.x * 128) {
        int i = base + f;
        float sv = 0.0f, tv = 0.0f;
        if (i < n) {
            float di = g_dinv[i];
            sv = di * (g_sacc[i] + g_y[i]);
            tv = di * (g_tacc[i] + di);
        }
        __syncthreads();
        ssh[f] = sv;
        tsh[f] = tv;
        __syncthreads();
        int lim = min(128, n - base);
        #pragma unroll 8
        for (int j = 0; j < lim; j++) {
            float h = fmaxf(fmaf(ssh[j], w, bb), 0.0f);
            acc = fmaf(tsh[j], h, acc);
        }
    }
    atomicAdd(&g_v[f], acc);
}

// ---------------------------------------------------------------------------
// 6) out[o] = (1/N) * sum_f v[f]*W2[f,o] + b2[o]
__global__ void k_out(const float* __restrict__ W2, const float* __restrict__ b2,
                      float* __restrict__ out, int n) {
    __shared__ float vsh[HID];
    if (threadIdx.x < HID) vsh[threadIdx.x] = g_v[threadIdx.x];
    __syncthreads();
    int o = threadIdx.x;
    if (o < ODIM) {
        float acc = 0.0f;
        #pragma unroll 16
        for (int f = 0; f < HID; f++)
            acc = fmaf(vsh[f], W2[f * ODIM + o], acc);
        out[o] = acc * (1.0f / (float)n) + b2[o];
    }
}

// ---------------------------------------------------------------------------
extern "C" void kernel_launch(void* const* d_in, const int* in_sizes, int n_in,
                              void* d_out, int out_size) {
    const float* x  = (const float*)d_in[0];   // [N,1]
    const int*   ei = (const int*)d_in[1];     // [2,E]: row half then col half
    const float* W1 = (const float*)d_in[2];   // [1,128]
    const float* b1 = (const float*)d_in[3];   // [128]
    const float* W2 = (const float*)d_in[4];   // [128,400]
    const float* b2 = (const float*)d_in[5];   // [400]
    float* out = (float*)d_out;                // [400]

    int n = in_sizes[0];
    int E = in_sizes[1] / 2;
    const int* row = ei;
    const int* col = ei + E;
    int vec_ok = ((E & 3) == 0) ? 1 : 0;       // col half stays 16B-aligned

    int nb_n = (n + 255) / 256;
    int eth  = (E + 3) / 4;                    // 4 edges per thread
    int nb_e = (eth + 255) / 256;              // ~1563 blocks

    k_init<<<nb_n, 256>>>(n);
    k_deg <<<nb_e, 256>>>(col, E, vec_ok);
    k_dinv<<<nb_n, 256>>>(x, n);
    k_edge<<<nb_e, 256>>>(row, col, E, vec_ok);
    k_v   <<<448, 128>>>(W1, b1, n);
    k_out <<<1, 512>>>(W2, b2, out, n);
}